// round 6
// baseline (speedup 1.0000x reference)
#include <cuda_runtime.h>

// Warping_65094524339056 — Round 6: big tile (16x16x32), 1024 threads,
// 2 blocks/SM (64 warps), odd z-stride for bank spread.
//
// out[b,x,y,z] = trilinear(image[b], (x,y,z)+ddf[b,x,y,z,:]), clamp [0,127].
//
//  * Image tile with halo 4 (+1) staged in SMEM: 25 x 25 x 41 = 102.5 KB.
//    SZ=41 (odd, coprime 32) -> good bank spread for jittered row offsets.
//  * Staging: warp-per-row, clamps warp-uniform, border clamp baked into tile.
//  * Compute: clamp-free fast path (bitwise == reference inside halo);
//    rare out-of-halo voxels take the clamped global path.

#define DMASK 127
#define H    4
#define EX   25
#define EY   25
#define EZV  41
#define SZ   41
#define SXY  (EY*SZ)            // 1025
#define TILE_ELEMS (EX*SXY)     // 25625 floats = 102500 B
#define NROWS (EX*EY)           // 625
#define BLOCK 1024
#define VPT   8

__device__ __forceinline__ float clampf(float v) {
    return fminf(fmaxf(v, 0.0f), 127.0f);
}

__global__ __launch_bounds__(BLOCK, 2) void warp_kernel(
    const float* __restrict__ ddf,
    const float* __restrict__ image,
    float* __restrict__ out)
{
    extern __shared__ float tile[];

    int tid = threadIdx.x;
    int bid = blockIdx.x;
    // 8(x) x 8(y) x 4(z) tiles x 4 batches = 1024 blocks
    int tz = bid & 3;
    int ty = (bid >> 2) & 7;
    int tx = (bid >> 5) & 7;
    int b  = bid >> 8;

    int X0 = tx << 4;
    int Y0 = ty << 4;
    int Z0 = tz << 5;

    const float* img = image + ((long long)b << 21);

    // ---- stage tile: one row per warp; clamps warp-uniform ----
    {
        int wid  = tid >> 5;      // 0..31
        int lane = tid & 31;
        for (int r = wid; r < NROWS; r += 32) {
            int sy = r % EY;
            int sx = r / EY;
            int gx = min(max(X0 - H + sx, 0), DMASK);
            int gy = min(max(Y0 - H + sy, 0), DMASK);
            const float* rowp = img + (gx << 14) + (gy << 7);
            float* srow = tile + r * SZ;
            int gz0 = max(Z0 - H + lane, 0);              // upper <= 123
            srow[lane] = __ldg(rowp + gz0);
            if (lane < EZV - 32) {                        // 9 tail elements
                int gz1 = min(Z0 - H + 32 + lane, DMASK); // lower >= 28
                srow[lane + 32] = __ldg(rowp + gz1);
            }
        }
    }
    __syncthreads();

    // ---- compute: 8 voxels/thread; warp lanes are z-consecutive ----
    int lz  = tid & 31;
    int ly  = (tid >> 5) & 15;
    int lxh = tid >> 9;               // 0 or 1; x = X0 + lxh + 2*v

    int y = Y0 + ly;
    int z = Z0 + lz;
    int xb = X0 + lxh;

    int vid0 = (xb << 14) + (y << 7) + z;
    const float* ddfb = ddf + ((long long)b << 21) * 3;
    float*       outb = out + ((long long)b << 21);

    const float yf = (float)y;
    const float zf = (float)z;
    const int ox = X0 - H, oy = Y0 - H, oz = Z0 - H;

#pragma unroll
    for (int v = 0; v < VPT; v++) {
        int vid = vid0 + (v << 15);               // x += 2 per iter

        const float* dp = ddfb + (long long)vid * 3;
        float dx = __ldg(dp);
        float dy = __ldg(dp + 1);
        float dz = __ldg(dp + 2);

        float fx = (float)(xb + 2 * v) + dx;      // same fp as reference
        float fy = yf + dy;
        float fz = zf + dz;

        int ix0 = __float2int_rd(fx);
        int iy0 = __float2int_rd(fy);
        int iz0 = __float2int_rd(fz);
        float wx = fx - (float)ix0;
        float wy = fy - (float)iy0;
        float wz = fz - (float)iz0;

        int sx0 = ix0 - ox;
        int sy0 = iy0 - oy;
        int sz0 = iz0 - oz;

        bool ok = ((unsigned)sx0 <= (unsigned)(EX - 2)) &
                  ((unsigned)sy0 <= (unsigned)(EY - 2)) &
                  ((unsigned)sz0 <= (unsigned)(EZV - 2));

        float v000, v001, v010, v011, v100, v101, v110, v111;
        if (ok) {
            int base = (sx0 * EY + sy0) * SZ + sz0;
            v000 = tile[base];
            v001 = tile[base + 1];
            v010 = tile[base + SZ];
            v011 = tile[base + SZ + 1];
            v100 = tile[base + SXY];
            v101 = tile[base + SXY + 1];
            v110 = tile[base + SXY + SZ];
            v111 = tile[base + SXY + SZ + 1];
        } else {
            // rare: beyond halo -> clamped global gather (matches reference)
            float cfx = clampf(fx), cfy = clampf(fy), cfz = clampf(fz);
            ix0 = (int)cfx;  iy0 = (int)cfy;  iz0 = (int)cfz;
            wx = cfx - (float)ix0;
            wy = cfy - (float)iy0;
            wz = cfz - (float)iz0;
            int ix1 = min(ix0 + 1, DMASK);
            int iy1 = min(iy0 + 1, DMASK);
            int iz1 = min(iz0 + 1, DMASK);
            int g00 = (ix0 << 14) + (iy0 << 7);
            int g01 = (ix0 << 14) + (iy1 << 7);
            int g10 = (ix1 << 14) + (iy0 << 7);
            int g11 = (ix1 << 14) + (iy1 << 7);
            v000 = __ldg(img + g00 + iz0);  v001 = __ldg(img + g00 + iz1);
            v010 = __ldg(img + g01 + iz0);  v011 = __ldg(img + g01 + iz1);
            v100 = __ldg(img + g10 + iz0);  v101 = __ldg(img + g10 + iz1);
            v110 = __ldg(img + g11 + iz0);  v111 = __ldg(img + g11 + iz1);
        }

        float c00 = v000 + wz * (v001 - v000);
        float c01 = v010 + wz * (v011 - v010);
        float c10 = v100 + wz * (v101 - v100);
        float c11 = v110 + wz * (v111 - v110);
        float c0  = c00 + wy * (c01 - c00);
        float c1  = c10 + wy * (c11 - c10);
        outb[vid] = c0 + wx * (c1 - c0);
    }
}

extern "C" void kernel_launch(void* const* d_in, const int* in_sizes, int n_in,
                              void* d_out, int out_size)
{
    const float* ddf   = (const float*)d_in[0];
    const float* image = (const float*)d_in[1];
    float* out = (float*)d_out;

    size_t smem = TILE_ELEMS * sizeof(float);   // 102500 B
    cudaFuncSetAttribute(warp_kernel,
                         cudaFuncAttributeMaxDynamicSharedMemorySize, (int)smem);

    warp_kernel<<<1024, BLOCK, smem>>>(ddf, image, out);
}

// round 7
// speedup vs baseline: 1.1634x; 1.1634x over previous
#include <cuda_runtime.h>

// Warping_65094524339056 — Round 7: R5 tile + software-pipelined ddf loads.
//
// Diagnosis: R2/R5/R6 all ~66us with no pipe >60% busy and occupancy gains
// doing nothing -> latency-bound at regs=32 (no MLP). Fix: 42-reg budget +
// prefetch-distance-2 ring for the ddf stream + streaming cache hints.

#define DMASK 127
#define H    4
#define EX   25
#define EY   17
#define EZV  41
#define SZ   41                  // odd stride: bank spread
#define SXY  (EY*SZ)             // 697
#define TILE_ELEMS (EX*SXY)      // 17425 floats = 69.7 KB
#define NROWS (EX*EY)            // 425
#define BLOCK 512
#define VPT   8

__device__ __forceinline__ float clampf(float v) {
    return fminf(fmaxf(v, 0.0f), 127.0f);
}

__global__ __launch_bounds__(BLOCK, 3) void warp_kernel(
    const float* __restrict__ ddf,
    const float* __restrict__ image,
    float* __restrict__ out)
{
    extern __shared__ float tile[];

    int tid = threadIdx.x;
    int bid = blockIdx.x;
    // 8(x) x 16(y) x 4(z) tiles x 4 batches = 2048 blocks
    int tz = bid & 3;
    int ty = (bid >> 2) & 15;
    int tx = (bid >> 6) & 7;
    int b  = bid >> 9;

    int X0 = tx << 4;
    int Y0 = ty << 3;
    int Z0 = tz << 5;

    const float* img = image + ((long long)b << 21);

    // ---- stage tile: one row per warp per step; clamps warp-uniform ----
    {
        int wid  = tid >> 5;
        int lane = tid & 31;
        for (int r = wid; r < NROWS; r += 16) {
            int sy = r % EY;
            int sx = r / EY;
            int gx = min(max(X0 - H + sx, 0), DMASK);
            int gy = min(max(Y0 - H + sy, 0), DMASK);
            const float* rowp = img + (gx << 14) + (gy << 7);
            float* srow = tile + r * SZ;
            int gz0 = max(Z0 - H + lane, 0);
            srow[lane] = __ldg(rowp + gz0);
            if (lane < EZV - 32) {
                int gz1 = min(Z0 - H + 32 + lane, DMASK);
                srow[lane + 32] = __ldg(rowp + gz1);
            }
        }
    }
    __syncthreads();

    // ---- compute: 8 voxels/thread; lanes z-consecutive ----
    int lz  = tid & 31;
    int ly  = (tid >> 5) & 7;
    int lxh = tid >> 8;                // 0/1; x = X0 + lxh + 2*v

    int y = Y0 + ly;
    int z = Z0 + lz;
    int xb = X0 + lxh;

    int vid0 = (xb << 14) + (y << 7) + z;
    const float* ddfb = ddf + ((long long)b << 21) * 3;
    float*       outb = out + ((long long)b << 21);
    const float* dp0  = ddfb + (long long)vid0 * 3;
    const int DSTRIDE = 3 << 15;       // ddf elems per x+=2 step

    const float yf = (float)y;
    const float zf = (float)z;
    const int ox = X0 - H, oy = Y0 - H, oz = Z0 - H;

    // ---- prefetch ring (distance 2) for the ddf stream ----
    float rdx[2], rdy[2], rdz[2];
    {
        const float* p0 = dp0;
        const float* p1 = dp0 + DSTRIDE;
        rdx[0] = __ldcs(p0);  rdy[0] = __ldcs(p0 + 1);  rdz[0] = __ldcs(p0 + 2);
        rdx[1] = __ldcs(p1);  rdy[1] = __ldcs(p1 + 1);  rdz[1] = __ldcs(p1 + 2);
    }

#pragma unroll
    for (int v = 0; v < VPT; v++) {
        int slot = v & 1;
        float dx = rdx[slot], dy = rdy[slot], dz = rdz[slot];

        // issue next prefetch BEFORE the dependent work of this iteration
        if (v + 2 < VPT) {
            const float* pn = dp0 + (v + 2) * DSTRIDE;
            rdx[slot] = __ldcs(pn);
            rdy[slot] = __ldcs(pn + 1);
            rdz[slot] = __ldcs(pn + 2);
        }

        int vid = vid0 + (v << 15);

        float fx = (float)(xb + 2 * v) + dx;     // same fp as reference
        float fy = yf + dy;
        float fz = zf + dz;

        int ix0 = __float2int_rd(fx);
        int iy0 = __float2int_rd(fy);
        int iz0 = __float2int_rd(fz);
        float wx = fx - (float)ix0;
        float wy = fy - (float)iy0;
        float wz = fz - (float)iz0;

        int sx0 = ix0 - ox;
        int sy0 = iy0 - oy;
        int sz0 = iz0 - oz;

        bool ok = ((unsigned)sx0 <= (unsigned)(EX - 2)) &
                  ((unsigned)sy0 <= (unsigned)(EY - 2)) &
                  ((unsigned)sz0 <= (unsigned)(EZV - 2));

        float v000, v001, v010, v011, v100, v101, v110, v111;
        if (ok) {
            int base = (sx0 * EY + sy0) * SZ + sz0;
            v000 = tile[base];
            v001 = tile[base + 1];
            v010 = tile[base + SZ];
            v011 = tile[base + SZ + 1];
            v100 = tile[base + SXY];
            v101 = tile[base + SXY + 1];
            v110 = tile[base + SXY + SZ];
            v111 = tile[base + SXY + SZ + 1];
        } else {
            // rare: beyond halo -> clamped global gather (matches reference)
            float cfx = clampf(fx), cfy = clampf(fy), cfz = clampf(fz);
            ix0 = (int)cfx;  iy0 = (int)cfy;  iz0 = (int)cfz;
            wx = cfx - (float)ix0;
            wy = cfy - (float)iy0;
            wz = cfz - (float)iz0;
            int ix1 = min(ix0 + 1, DMASK);
            int iy1 = min(iy0 + 1, DMASK);
            int iz1 = min(iz0 + 1, DMASK);
            int g00 = (ix0 << 14) + (iy0 << 7);
            int g01 = (ix0 << 14) + (iy1 << 7);
            int g10 = (ix1 << 14) + (iy0 << 7);
            int g11 = (ix1 << 14) + (iy1 << 7);
            v000 = __ldg(img + g00 + iz0);  v001 = __ldg(img + g00 + iz1);
            v010 = __ldg(img + g01 + iz0);  v011 = __ldg(img + g01 + iz1);
            v100 = __ldg(img + g10 + iz0);  v101 = __ldg(img + g10 + iz1);
            v110 = __ldg(img + g11 + iz0);  v111 = __ldg(img + g11 + iz1);
        }

        float c00 = v000 + wz * (v001 - v000);
        float c01 = v010 + wz * (v011 - v010);
        float c10 = v100 + wz * (v101 - v100);
        float c11 = v110 + wz * (v111 - v110);
        float c0  = c00 + wy * (c01 - c00);
        float c1  = c10 + wy * (c11 - c10);
        __stcs(&outb[vid], c0 + wx * (c1 - c0));
    }
}

extern "C" void kernel_launch(void* const* d_in, const int* in_sizes, int n_in,
                              void* d_out, int out_size)
{
    const float* ddf   = (const float*)d_in[0];
    const float* image = (const float*)d_in[1];
    float* out = (float*)d_out;

    size_t smem = TILE_ELEMS * sizeof(float);   // 69700 B
    cudaFuncSetAttribute(warp_kernel,
                         cudaFuncAttributeMaxDynamicSharedMemorySize, (int)smem);

    warp_kernel<<<2048, BLOCK, smem>>>(ddf, image, out);
}